// round 1
// baseline (speedup 1.0000x reference)
#include <cuda_runtime.h>
#include <math.h>

// Problem constants: B=2, N=2048, C=1024, H=16, D=64
// Q/K/V layout: [bh=32][n=2048][128] where dim 0..63 = real part, 64..127 = imag part.

#define ATTN_SMEM 103424  // (2*128*68 + 64*132) * 4 bytes

__device__ float g_q[32 * 2048 * 128];
__device__ float g_k[32 * 2048 * 128];
__device__ float g_v[32 * 2048 * 128];
__device__ float g_ao[32 * 2048 * 128];   // attention output, same layout
__device__ float g_z[4096 * 2048];        // merged heads: [out_r | out_i] per token
__device__ float g_wc[1024 * 2048];       // combined output weight
__device__ float g_fb[1024];              // combined output bias

// ---------------------------------------------------------------------------
// Combined output weight: Wc[o][k<1024]   = or_w[o][k]      + 0.1*oi_w[o][k]
//                         Wc[o][k>=1024]  = 0.1*or_w[o][k'] -     oi_w[o][k']
// bias fb[o] = 1.1*or_b[o] - 0.9*oi_b[o]
// ---------------------------------------------------------------------------
__global__ void __launch_bounds__(256) make_wc_kernel(
    const float* __restrict__ orw, const float* __restrict__ oiw,
    const float* __restrict__ orb, const float* __restrict__ oib)
{
    int idx = blockIdx.x * 256 + threadIdx.x;   // float4 index over [1024][2048]
    int o = idx >> 9;                            // 512 float4 per row
    int k = (idx & 511) << 2;
    float4 r;
    if (k < 1024) {
        float4 a = *(const float4*)(orw + o * 1024 + k);
        float4 b = *(const float4*)(oiw + o * 1024 + k);
        r.x = a.x + 0.1f * b.x; r.y = a.y + 0.1f * b.y;
        r.z = a.z + 0.1f * b.z; r.w = a.w + 0.1f * b.w;
    } else {
        int kk = k - 1024;
        float4 a = *(const float4*)(orw + o * 1024 + kk);
        float4 b = *(const float4*)(oiw + o * 1024 + kk);
        r.x = 0.1f * a.x - b.x; r.y = 0.1f * a.y - b.y;
        r.z = 0.1f * a.z - b.z; r.w = 0.1f * a.w - b.w;
    }
    *(float4*)(g_wc + o * 2048 + k) = r;
    if ((idx & 511) == 0)
        g_fb[o] = 1.1f * orb[o] - 0.9f * oib[o];
}

// ---------------------------------------------------------------------------
// Input projection GEMM. Computes Y[m, o] = sum_c X[m,c] * W[o,c] + bias[o]
// for o in [0,2048): o<1024 -> real weight, o>=1024 -> imag weight.
// Output scattered into [bh][n][128] layout (which selects g_q / g_k / g_v).
// BM=BN=128, BK=16, 256 threads, 8x8 per thread.
// ---------------------------------------------------------------------------
__global__ void __launch_bounds__(256) proj_gemm_kernel(
    const float* __restrict__ X,
    const float* __restrict__ Wr, const float* __restrict__ Wi,
    const float* __restrict__ br, const float* __restrict__ bi,
    int which)
{
    __shared__ float As[16][132];
    __shared__ float Bs[16][132];
    float* Out = (which == 0) ? g_q : (which == 1) ? g_k : g_v;

    const int t  = threadIdx.x;
    const int tx = t & 15, ty = t >> 4;
    const int m0 = blockIdx.y * 128;
    const int o0 = blockIdx.x * 128;
    const int lr = t >> 2;            // 0..63
    const int lk = (t & 3) * 4;       // 0,4,8,12

    const float* a0p = X + (m0 + lr) * 1024;
    const float* a1p = X + (m0 + lr + 64) * 1024;
    int ow0 = o0 + lr;
    int ow1 = o0 + lr + 64;
    const float* b0p = (ow0 < 1024) ? (Wr + ow0 * 1024) : (Wi + (ow0 - 1024) * 1024);
    const float* b1p = (ow1 < 1024) ? (Wr + ow1 * 1024) : (Wi + (ow1 - 1024) * 1024);

    float acc[8][8];
    #pragma unroll
    for (int i = 0; i < 8; i++)
        #pragma unroll
        for (int j = 0; j < 8; j++) acc[i][j] = 0.f;

    for (int k0 = 0; k0 < 1024; k0 += 16) {
        float4 a0 = *(const float4*)(a0p + k0 + lk);
        float4 a1 = *(const float4*)(a1p + k0 + lk);
        float4 b0 = *(const float4*)(b0p + k0 + lk);
        float4 b1 = *(const float4*)(b1p + k0 + lk);
        As[lk + 0][lr] = a0.x; As[lk + 1][lr] = a0.y; As[lk + 2][lr] = a0.z; As[lk + 3][lr] = a0.w;
        As[lk + 0][lr + 64] = a1.x; As[lk + 1][lr + 64] = a1.y; As[lk + 2][lr + 64] = a1.z; As[lk + 3][lr + 64] = a1.w;
        Bs[lk + 0][lr] = b0.x; Bs[lk + 1][lr] = b0.y; Bs[lk + 2][lr] = b0.z; Bs[lk + 3][lr] = b0.w;
        Bs[lk + 0][lr + 64] = b1.x; Bs[lk + 1][lr + 64] = b1.y; Bs[lk + 2][lr + 64] = b1.z; Bs[lk + 3][lr + 64] = b1.w;
        __syncthreads();
        #pragma unroll
        for (int k = 0; k < 16; k++) {
            float a[8], b[8];
            *(float4*)&a[0] = *(const float4*)&As[k][ty * 8];
            *(float4*)&a[4] = *(const float4*)&As[k][ty * 8 + 4];
            *(float4*)&b[0] = *(const float4*)&Bs[k][tx * 8];
            *(float4*)&b[4] = *(const float4*)&Bs[k][tx * 8 + 4];
            #pragma unroll
            for (int i = 0; i < 8; i++)
                #pragma unroll
                for (int j = 0; j < 8; j++)
                    acc[i][j] = fmaf(a[i], b[j], acc[i][j]);
        }
        __syncthreads();
    }

    // epilogue: scatter into [bh][n][128]
    int oB = o0 + tx * 8;
    int part = oB >> 10;
    int oo = oB & 1023;
    int h = oo >> 6;
    int dd = oo & 63;
    const float* bptr = part ? bi : br;
    float4 bias0 = *(const float4*)(bptr + oo);
    float4 bias1 = *(const float4*)(bptr + oo + 4);
    #pragma unroll
    for (int i = 0; i < 8; i++) {
        int m = m0 + ty * 8 + i;
        int b_ = m >> 11;
        int nn = m & 2047;
        float* dst = Out + ((size_t)(((b_ << 4) + h) * 2048 + nn)) * 128 + part * 64 + dd;
        float4 r0 = make_float4(acc[i][0] + bias0.x, acc[i][1] + bias0.y,
                                acc[i][2] + bias0.z, acc[i][3] + bias0.w);
        float4 r1 = make_float4(acc[i][4] + bias1.x, acc[i][5] + bias1.y,
                                acc[i][6] + bias1.z, acc[i][7] + bias1.w);
        *(float4*)dst = r0;
        *(float4*)(dst + 4) = r1;
    }
}

// ---------------------------------------------------------------------------
// Fused complex-magnitude flash attention.
// Per block: one (bh, 64-query tile). Loops over 2048 keys in tiles of 64.
//   sr = qr.kr + qi.ki ; si = qi.kr - qr.ki ; mag = 0.125*sqrt(sr^2+si^2)
//   online softmax over mag; out = softmax @ [vr|vi]
// Threads: 16x16; scores 4x4/thread; output rows ty*4..+3, cols tx*4 & 64+tx*4.
// ---------------------------------------------------------------------------
__global__ void __launch_bounds__(256, 2) attn_kernel()
{
    extern __shared__ float sm[];
    float* Qs = sm;                   // [128][68] transposed (dim-major)
    float* KP = sm + 128 * 68;        // [128][68] K transposed; reused as P [64][68]
    float* Vs = sm + 2 * 128 * 68;    // [64][132]

    const int t  = threadIdx.x;
    const int tx = t & 15;
    const int ty = t >> 4;
    const int bh = blockIdx.y;
    const int q0 = blockIdx.x * 64;

    const float* Qg = g_q + ((size_t)bh * 2048 + q0) * 128;
    const float* Kg = g_k + (size_t)bh * 2048 * 128;
    const float* Vg = g_v + (size_t)bh * 2048 * 128;

    const int lr = t >> 2;   // 0..63
    const int lc = t & 3;    // 0..3

    // load Q tile, transposing into Qs[d][n]
    #pragma unroll
    for (int i = 0; i < 8; i++) {
        int d4 = lc + i * 4;
        float4 v = *(const float4*)(Qg + lr * 128 + d4 * 4);
        int d = d4 * 4;
        Qs[(d + 0) * 68 + lr] = v.x;
        Qs[(d + 1) * 68 + lr] = v.y;
        Qs[(d + 2) * 68 + lr] = v.z;
        Qs[(d + 3) * 68 + lr] = v.w;
    }

    float m_run[4], l_run[4];
    float oacc[4][8];
    #pragma unroll
    for (int i = 0; i < 4; i++) {
        m_run[i] = -3.0e38f;
        l_run[i] = 0.f;
        #pragma unroll
        for (int j = 0; j < 8; j++) oacc[i][j] = 0.f;
    }

    for (int k0 = 0; k0 < 2048; k0 += 64) {
        // load K (transposed) and V tiles
        #pragma unroll
        for (int i = 0; i < 8; i++) {
            int d4 = lc + i * 4;
            float4 v = *(const float4*)(Kg + (size_t)(k0 + lr) * 128 + d4 * 4);
            int d = d4 * 4;
            KP[(d + 0) * 68 + lr] = v.x;
            KP[(d + 1) * 68 + lr] = v.y;
            KP[(d + 2) * 68 + lr] = v.z;
            KP[(d + 3) * 68 + lr] = v.w;
        }
        #pragma unroll
        for (int i = 0; i < 8; i++) {
            int d4 = lc + i * 4;
            float4 v = *(const float4*)(Vg + (size_t)(k0 + lr) * 128 + d4 * 4);
            *(float4*)(Vs + lr * 132 + d4 * 4) = v;
        }
        __syncthreads();

        float sr[4][4], si[4][4];
        #pragma unroll
        for (int i = 0; i < 4; i++)
            #pragma unroll
            for (int j = 0; j < 4; j++) { sr[i][j] = 0.f; si[i][j] = 0.f; }

        #pragma unroll 8
        for (int k = 0; k < 64; k++) {
            float qrv[4], qiv[4], krv[4], kiv[4];
            *(float4*)qrv = *(const float4*)(Qs + k * 68 + ty * 4);
            *(float4*)qiv = *(const float4*)(Qs + (64 + k) * 68 + ty * 4);
            *(float4*)krv = *(const float4*)(KP + k * 68 + tx * 4);
            *(float4*)kiv = *(const float4*)(KP + (64 + k) * 68 + tx * 4);
            #pragma unroll
            for (int i = 0; i < 4; i++)
                #pragma unroll
                for (int j = 0; j < 4; j++) {
                    sr[i][j] = fmaf(qrv[i], krv[j], sr[i][j]);
                    sr[i][j] = fmaf(qiv[i], kiv[j], sr[i][j]);
                    si[i][j] = fmaf(qiv[i], krv[j], si[i][j]);
                    si[i][j] = fmaf(-qrv[i], kiv[j], si[i][j]);
                }
        }
        __syncthreads();   // all done reading K region of KP

        // magnitude + online softmax; write P into KP
        #pragma unroll
        for (int i = 0; i < 4; i++) {
            float rowmax = -3.0e38f;
            #pragma unroll
            for (int j = 0; j < 4; j++) {
                float mag = 0.125f * sqrtf(sr[i][j] * sr[i][j] + si[i][j] * si[i][j]);
                sr[i][j] = mag;
                rowmax = fmaxf(rowmax, mag);
            }
            #pragma unroll
            for (int off = 8; off >= 1; off >>= 1)
                rowmax = fmaxf(rowmax, __shfl_xor_sync(0xffffffffu, rowmax, off, 16));
            float mnew = fmaxf(m_run[i], rowmax);
            float corr = __expf(m_run[i] - mnew);
            m_run[i] = mnew;
            float rsum = 0.f;
            #pragma unroll
            for (int j = 0; j < 4; j++) {
                float e = __expf(sr[i][j] - mnew);
                sr[i][j] = e;
                rsum += e;
            }
            #pragma unroll
            for (int off = 8; off >= 1; off >>= 1)
                rsum += __shfl_xor_sync(0xffffffffu, rsum, off, 16);
            l_run[i] = l_run[i] * corr + rsum;
            #pragma unroll
            for (int j = 0; j < 8; j++) oacc[i][j] *= corr;
            *(float4*)(KP + (ty * 4 + i) * 68 + tx * 4) = *(float4*)&sr[i][0];
        }
        __syncthreads();   // P visible

        // out += P @ Vcat
        #pragma unroll 8
        for (int kk = 0; kk < 64; kk++) {
            float v0[4], v1[4];
            *(float4*)v0 = *(const float4*)(Vs + kk * 132 + tx * 4);
            *(float4*)v1 = *(const float4*)(Vs + kk * 132 + 64 + tx * 4);
            #pragma unroll
            for (int i = 0; i < 4; i++) {
                float pv = KP[(ty * 4 + i) * 68 + kk];
                #pragma unroll
                for (int j = 0; j < 4; j++) {
                    oacc[i][j]     = fmaf(pv, v0[j], oacc[i][j]);
                    oacc[i][4 + j] = fmaf(pv, v1[j], oacc[i][4 + j]);
                }
            }
        }
        __syncthreads();   // done with P and V before next tile overwrites
    }

    float* Og = g_ao + ((size_t)bh * 2048 + q0) * 128;
    #pragma unroll
    for (int i = 0; i < 4; i++) {
        float inv = 1.f / l_run[i];
        float o0v[4], o1v[4];
        #pragma unroll
        for (int j = 0; j < 4; j++) {
            o0v[j] = oacc[i][j] * inv;
            o1v[j] = oacc[i][4 + j] * inv;
        }
        *(float4*)(Og + (ty * 4 + i) * 128 + tx * 4) = *(float4*)o0v;
        *(float4*)(Og + (ty * 4 + i) * 128 + 64 + tx * 4) = *(float4*)o1v;
    }
}

// ---------------------------------------------------------------------------
// Merge heads: g_ao [bh][n][128] -> g_z [b*2048+n][2048] = [out_r(1024) | out_i(1024)]
// ---------------------------------------------------------------------------
__global__ void __launch_bounds__(256) repack_kernel()
{
    int idx = blockIdx.x * 256 + threadIdx.x;   // float4 index, 2M total
    int d4 = idx & 31;
    int nn = (idx >> 5) & 2047;
    int bh = idx >> 16;
    float4 v = *(const float4*)(g_ao + (size_t)idx * 4);
    int b_ = bh >> 4, h = bh & 15;
    int d = d4 << 2;
    int part = d >> 6;
    int dl = d & 63;
    int col = part * 1024 + h * 64 + dl;
    *(float4*)(g_z + ((size_t)(b_ * 2048 + nn)) * 2048 + col) = v;
}

// ---------------------------------------------------------------------------
// Final GEMM: out[m][o] = sum_k g_z[m][k] * g_wc[o][k] + g_fb[o]
// M=4096, O=1024, K=2048.
// ---------------------------------------------------------------------------
__global__ void __launch_bounds__(256) final_gemm_kernel(float* __restrict__ Outp)
{
    __shared__ float As[16][132];
    __shared__ float Bs[16][132];

    const int t  = threadIdx.x;
    const int tx = t & 15, ty = t >> 4;
    const int m0 = blockIdx.y * 128;
    const int o0 = blockIdx.x * 128;
    const int lr = t >> 2;
    const int lk = (t & 3) * 4;

    const float* a0p = g_z + (size_t)(m0 + lr) * 2048;
    const float* a1p = g_z + (size_t)(m0 + lr + 64) * 2048;
    const float* b0p = g_wc + (size_t)(o0 + lr) * 2048;
    const float* b1p = g_wc + (size_t)(o0 + lr + 64) * 2048;

    float acc[8][8];
    #pragma unroll
    for (int i = 0; i < 8; i++)
        #pragma unroll
        for (int j = 0; j < 8; j++) acc[i][j] = 0.f;

    for (int k0 = 0; k0 < 2048; k0 += 16) {
        float4 a0 = *(const float4*)(a0p + k0 + lk);
        float4 a1 = *(const float4*)(a1p + k0 + lk);
        float4 b0 = *(const float4*)(b0p + k0 + lk);
        float4 b1 = *(const float4*)(b1p + k0 + lk);
        As[lk + 0][lr] = a0.x; As[lk + 1][lr] = a0.y; As[lk + 2][lr] = a0.z; As[lk + 3][lr] = a0.w;
        As[lk + 0][lr + 64] = a1.x; As[lk + 1][lr + 64] = a1.y; As[lk + 2][lr + 64] = a1.z; As[lk + 3][lr + 64] = a1.w;
        Bs[lk + 0][lr] = b0.x; Bs[lk + 1][lr] = b0.y; Bs[lk + 2][lr] = b0.z; Bs[lk + 3][lr] = b0.w;
        Bs[lk + 0][lr + 64] = b1.x; Bs[lk + 1][lr + 64] = b1.y; Bs[lk + 2][lr + 64] = b1.z; Bs[lk + 3][lr + 64] = b1.w;
        __syncthreads();
        #pragma unroll
        for (int k = 0; k < 16; k++) {
            float a[8], b[8];
            *(float4*)&a[0] = *(const float4*)&As[k][ty * 8];
            *(float4*)&a[4] = *(const float4*)&As[k][ty * 8 + 4];
            *(float4*)&b[0] = *(const float4*)&Bs[k][tx * 8];
            *(float4*)&b[4] = *(const float4*)&Bs[k][tx * 8 + 4];
            #pragma unroll
            for (int i = 0; i < 8; i++)
                #pragma unroll
                for (int j = 0; j < 8; j++)
                    acc[i][j] = fmaf(a[i], b[j], acc[i][j]);
        }
        __syncthreads();
    }

    float4 fb0 = *(const float4*)(g_fb + o0 + tx * 8);
    float4 fb1 = *(const float4*)(g_fb + o0 + tx * 8 + 4);
    #pragma unroll
    for (int i = 0; i < 8; i++) {
        int m = m0 + ty * 8 + i;
        float* dst = Outp + (size_t)m * 1024 + o0 + tx * 8;
        float4 r0 = make_float4(acc[i][0] + fb0.x, acc[i][1] + fb0.y,
                                acc[i][2] + fb0.z, acc[i][3] + fb0.w);
        float4 r1 = make_float4(acc[i][4] + fb1.x, acc[i][5] + fb1.y,
                                acc[i][6] + fb1.z, acc[i][7] + fb1.w);
        *(float4*)dst = r0;
        *(float4*)(dst + 4) = r1;
    }
}

// ---------------------------------------------------------------------------
extern "C" void kernel_launch(void* const* d_in, const int* in_sizes, int n_in,
                              void* d_out, int out_size)
{
    const float* x    = (const float*)d_in[0];
    const float* qr_w = (const float*)d_in[1];
    const float* qr_b = (const float*)d_in[2];
    const float* qi_w = (const float*)d_in[3];
    const float* qi_b = (const float*)d_in[4];
    const float* kr_w = (const float*)d_in[5];
    const float* kr_b = (const float*)d_in[6];
    const float* ki_w = (const float*)d_in[7];
    const float* ki_b = (const float*)d_in[8];
    const float* vr_w = (const float*)d_in[9];
    const float* vr_b = (const float*)d_in[10];
    const float* vi_w = (const float*)d_in[11];
    const float* vi_b = (const float*)d_in[12];
    const float* or_w = (const float*)d_in[13];
    const float* or_b = (const float*)d_in[14];
    const float* oi_w = (const float*)d_in[15];
    const float* oi_b = (const float*)d_in[16];
    float* out = (float*)d_out;

    cudaFuncSetAttribute(attn_kernel, cudaFuncAttributeMaxDynamicSharedMemorySize, ATTN_SMEM);

    make_wc_kernel<<<2048, 256>>>(or_w, oi_w, or_b, oi_b);

    dim3 pg(16, 32);   // (O tiles = 2048/128, M tiles = 4096/128)
    proj_gemm_kernel<<<pg, 256>>>(x, qr_w, qi_w, qr_b, qi_b, 0);
    proj_gemm_kernel<<<pg, 256>>>(x, kr_w, ki_w, kr_b, ki_b, 1);
    proj_gemm_kernel<<<pg, 256>>>(x, vr_w, vi_w, vr_b, vi_b, 2);

    attn_kernel<<<dim3(32, 32), 256, ATTN_SMEM>>>();

    repack_kernel<<<8192, 256>>>();

    final_gemm_kernel<<<dim3(8, 32), 256>>>(out);
}